// round 1
// baseline (speedup 1.0000x reference)
#include <cuda_runtime.h>

#define BB 2
#define NN 2048
#define DD 64
#define AAN 16
#define EE 2
#define TT 5
#define HH 128
#define EN (EE*NN)       /* 4096 */
#define ADJW (2*EN)      /* 8192 */

// Scratch (device globals: no allocation allowed)
__device__ float g_h[BB*NN*DD];
__device__ float g_ins[BB*EN*DD];
__device__ float g_outs[BB*EN*DD];
__device__ float g_ain[BB*NN*DD];
__device__ float g_aout[BB*NN*DD];

__device__ __forceinline__ float sigf(float x) {
    return 1.0f / (1.0f + __expf(-x));
}

// ---------------- init: h = prop_state ----------------
__global__ void k_init(const float4* __restrict__ ps) {
    int i = blockIdx.x * 256 + threadIdx.x;   // 65536 float4 total
    ((float4*)g_h)[i] = ps[i];
}

// ---------------- edge transforms: ins/outs = h @ W_in[e] + b ----------------
// grid (64, E, B), 256 threads; tile of 32 n-rows
__global__ void k_transform(const float* __restrict__ Win, const float* __restrict__ bin,
                            const float* __restrict__ Wout, const float* __restrict__ bout) {
    __shared__ float sWi[64*64];
    __shared__ float sWo[64*64];
    __shared__ float sh[32*64];
    __shared__ float sbi[64], sbo[64];
    int ntile = blockIdx.x, e = blockIdx.y, b = blockIdx.z;
    int tid = threadIdx.x;

    const float4* wi4 = (const float4*)(Win + e*4096);
    const float4* wo4 = (const float4*)(Wout + e*4096);
    #pragma unroll
    for (int i = 0; i < 4; i++) {
        ((float4*)sWi)[tid + i*256] = wi4[tid + i*256];
        ((float4*)sWo)[tid + i*256] = wo4[tid + i*256];
    }
    const float4* h4 = (const float4*)(g_h + (b*NN + ntile*32)*64);
    #pragma unroll
    for (int i = 0; i < 2; i++) ((float4*)sh)[tid + i*256] = h4[tid + i*256];
    if (tid < 64) { sbi[tid] = bin[e*64 + tid]; sbo[tid] = bout[e*64 + tid]; }
    __syncthreads();

    int col = tid & 63, rg = tid >> 6;
    float* insp = g_ins  + ((b*EE + e)*NN + ntile*32)*64;
    float* outp = g_outs + ((b*EE + e)*NN + ntile*32)*64;
    for (int r = rg; r < 32; r += 4) {
        float ai = sbi[col], ao = sbo[col];
        #pragma unroll
        for (int k = 0; k < 64; k++) {
            float hv = sh[r*64 + k];
            ai += hv * sWi[k*64 + col];
            ao += hv * sWo[k*64 + col];
        }
        insp[r*64 + col] = ai;
        outp[r*64 + col] = ao;
    }
}

// ---------------- big GEMM: a = Adj_half (2048x4096) @ msgs (4096x64) ----------------
// grid (32, 2, B): (row-tile of 64, dir, batch); 256 threads; 4x4 microtile
__global__ void k_bigmm(const float* __restrict__ adj) {
    __shared__ float sA[32*65];   // transposed A tile: sA[k][row], pad 65 (conflict-free)
    __shared__ float sB[32*64];   // sB[k][d]
    int mt = blockIdx.x, dir = blockIdx.y, b = blockIdx.z;
    int tid = threadIdx.x;
    int tx = tid & 15, ty = tid >> 4;

    const float* src = (dir ? g_outs : g_ins) + b*EN*64;
    const float* arow = adj + ((size_t)b*NN + mt*64)*ADJW + dir*EN;

    float acc[4][4] = {};
    for (int k0 = 0; k0 < EN; k0 += 32) {
        #pragma unroll
        for (int i = 0; i < 2; i++) {
            int idx = tid + i*256;
            int rl = idx >> 3, kq = idx & 7;
            float4 v = *(const float4*)(arow + (size_t)rl*ADJW + k0 + kq*4);
            sA[(kq*4+0)*65 + rl] = v.x;
            sA[(kq*4+1)*65 + rl] = v.y;
            sA[(kq*4+2)*65 + rl] = v.z;
            sA[(kq*4+3)*65 + rl] = v.w;
        }
        #pragma unroll
        for (int i = 0; i < 2; i++) {
            int idx = tid + i*256;
            int ml = idx >> 4, dq = idx & 15;
            *(float4*)(sB + ml*64 + dq*4) = *(const float4*)(src + (k0+ml)*64 + dq*4);
        }
        __syncthreads();
        #pragma unroll
        for (int k = 0; k < 32; k++) {
            float4 b4 = *(float4*)(sB + k*64 + tx*4);
            #pragma unroll
            for (int i = 0; i < 4; i++) {
                float a = sA[k*65 + 4*ty + i];
                acc[i][0] += a * b4.x;
                acc[i][1] += a * b4.y;
                acc[i][2] += a * b4.z;
                acc[i][3] += a * b4.w;
            }
        }
        __syncthreads();
    }
    float* dst = (dir ? g_aout : g_ain) + (b*NN + mt*64)*64;
    #pragma unroll
    for (int i = 0; i < 4; i++) {
        float4 v = make_float4(acc[i][0], acc[i][1], acc[i][2], acc[i][3]);
        *(float4*)(dst + (4*ty + i)*64 + tx*4) = v;
    }
}

// ---------------- GRU gate update ----------------
// grid (128, B): 16 rows/block, 256 threads (col = tid&63, each thread: 4 rows)
__global__ void k_gru(const float* __restrict__ Wr, const float* __restrict__ br,
                      const float* __restrict__ Wz, const float* __restrict__ bz,
                      const float* __restrict__ Wh, const float* __restrict__ bh) {
    __shared__ float sa[16*192];
    __shared__ float sj[16*64];
    int nt = blockIdx.x, b = blockIdx.y;
    int tid = threadIdx.x;
    int n0 = nt * 16;

    const float* ain  = g_ain  + (b*NN + n0)*64;
    const float* aout = g_aout + (b*NN + n0)*64;
    const float* hp   = g_h    + (b*NN + n0)*64;
    for (int i = tid; i < 16*64; i += 256) {
        int r = i >> 6, c = i & 63;
        sa[r*192 + c]       = ain[r*64 + c];
        sa[r*192 + 64 + c]  = aout[r*64 + c];
        sa[r*192 + 128 + c] = hp[r*64 + c];
    }
    __syncthreads();

    int col = tid & 63, rg = tid >> 6;
    float accR[4], accZ[4];
    #pragma unroll
    for (int ii = 0; ii < 4; ii++) { accR[ii] = br[col]; accZ[ii] = bz[col]; }
    #pragma unroll 8
    for (int k = 0; k < 192; k++) {
        float wr = Wr[k*64 + col], wz = Wz[k*64 + col];
        #pragma unroll
        for (int ii = 0; ii < 4; ii++) {
            float v = sa[(rg + 4*ii)*192 + k];
            accR[ii] += v * wr;
            accZ[ii] += v * wz;
        }
    }
    float zz[4], hold[4];
    #pragma unroll
    for (int ii = 0; ii < 4; ii++) {
        int r = rg + 4*ii;
        float rr = sigf(accR[ii]);
        zz[ii]  = sigf(accZ[ii]);
        hold[ii] = sa[r*192 + 128 + col];
        sj[r*64 + col] = rr * hold[ii];
    }
    __syncthreads();

    float accH[4];
    #pragma unroll
    for (int ii = 0; ii < 4; ii++) accH[ii] = bh[col];
    #pragma unroll 8
    for (int k = 0; k < 128; k++) {
        float wh = Wh[k*64 + col];
        #pragma unroll
        for (int ii = 0; ii < 4; ii++) accH[ii] += sa[(rg + 4*ii)*192 + k] * wh;
    }
    #pragma unroll 8
    for (int k = 0; k < 64; k++) {
        float wh = Wh[(128 + k)*64 + col];
        #pragma unroll
        for (int ii = 0; ii < 4; ii++) accH[ii] += sj[(rg + 4*ii)*64 + k] * wh;
    }
    float* hw = g_h + (b*NN + n0)*64;
    #pragma unroll
    for (int ii = 0; ii < 4; ii++) {
        int r = rg + 4*ii;
        float hh = tanhf(accH[ii]);
        hw[r*64 + col] = (1.0f - zz[ii]) * hold[ii] + zz[ii] * hh;
    }
}

// ---------------- readout: sum_j sigmoid([h,ann] @ Wo1 + bo1)_j * Wo2_j + bo2 ----------------
// grid 1024 blocks (4 rows each), 128 threads (one hidden unit each)
__global__ void k_out(const float* __restrict__ ann, const float* __restrict__ Wo1,
                      const float* __restrict__ bo1, const float* __restrict__ Wo2,
                      const float* __restrict__ bo2, float* __restrict__ out) {
    __shared__ float sx[4][80];
    __shared__ float sred[128];
    int blk = blockIdx.x;
    int b = blk >> 9;               // 512 blocks per batch
    int n0 = (blk & 511) * 4;
    int tid = threadIdx.x;

    for (int i = tid; i < 4*64; i += 128) {
        int r = i >> 6, c = i & 63;
        sx[r][c] = g_h[(b*NN + n0 + r)*64 + c];
    }
    if (tid < 64) {
        int r = tid >> 4, c = tid & 15;
        sx[r][64 + c] = ann[(b*NN + n0 + r)*AAN + c];
    }
    __syncthreads();

    float v[4];
    float w2 = Wo2[tid];
    float b1 = bo1[tid];
    #pragma unroll
    for (int r = 0; r < 4; r++) {
        float acc = b1;
        #pragma unroll 10
        for (int k = 0; k < 80; k++) acc += sx[r][k] * Wo1[k*128 + tid];
        v[r] = w2 * sigf(acc);
    }
    #pragma unroll
    for (int r = 0; r < 4; r++) {
        sred[tid] = v[r];
        __syncthreads();
        for (int s = 64; s > 0; s >>= 1) {
            if (tid < s) sred[tid] += sred[tid + s];
            __syncthreads();
        }
        if (tid == 0) out[b*NN + n0 + r] = sred[0] + bo2[0];
        __syncthreads();
    }
}

extern "C" void kernel_launch(void* const* d_in, const int* in_sizes, int n_in,
                              void* d_out, int out_size) {
    const float* prop = (const float*)d_in[0];
    const float* ann  = (const float*)d_in[1];
    const float* adj  = (const float*)d_in[2];
    const float* Win  = (const float*)d_in[3];
    const float* bin  = (const float*)d_in[4];
    const float* Wout = (const float*)d_in[5];
    const float* bout = (const float*)d_in[6];
    const float* Wr   = (const float*)d_in[7];
    const float* br   = (const float*)d_in[8];
    const float* Wz   = (const float*)d_in[9];
    const float* bz   = (const float*)d_in[10];
    const float* Wh   = (const float*)d_in[11];
    const float* bh   = (const float*)d_in[12];
    const float* Wo1  = (const float*)d_in[13];
    const float* bo1  = (const float*)d_in[14];
    const float* Wo2  = (const float*)d_in[15];
    const float* bo2  = (const float*)d_in[16];
    float* out = (float*)d_out;

    k_init<<<256, 256>>>((const float4*)prop);
    for (int t = 0; t < TT; t++) {
        k_transform<<<dim3(64, EE, BB), 256>>>(Win, bin, Wout, bout);
        k_bigmm<<<dim3(32, 2, BB), 256>>>(adj);
        k_gru<<<dim3(128, BB), 256>>>(Wr, br, Wz, bz, Wh, bh);
    }
    k_out<<<1024, 128>>>(ann, Wo1, bo1, Wo2, bo2, out);
}

// round 2
// speedup vs baseline: 1.0027x; 1.0027x over previous
#include <cuda_runtime.h>

#define BB 2
#define NN 2048
#define DD 64
#define AAN 16
#define EE 2
#define TT 5
#define HH 128
#define EN (EE*NN)       /* 4096 */
#define ADJW (2*EN)      /* 8192 */

// Scratch (device globals: no allocation allowed)
__device__ float g_h[BB*NN*DD];
__device__ float g_ins[BB*EN*DD];
__device__ float g_outs[BB*EN*DD];
__device__ float g_ain[BB*NN*DD];
__device__ float g_aout[BB*NN*DD];

__device__ __forceinline__ float sigf(float x) {
    return 1.0f / (1.0f + __expf(-x));
}

// ---------------- init: h = prop_state ----------------
__global__ void k_init(const float4* __restrict__ ps) {
    int i = blockIdx.x * 256 + threadIdx.x;   // 65536 float4 total
    ((float4*)g_h)[i] = ps[i];
}

// ---------------- edge transforms: ins/outs = h @ W_in[e] + b ----------------
// grid (64, E, B), 256 threads; tile of 32 n-rows
__global__ void k_transform(const float* __restrict__ Win, const float* __restrict__ bin,
                            const float* __restrict__ Wout, const float* __restrict__ bout) {
    __shared__ float sWi[64*64];
    __shared__ float sWo[64*64];
    __shared__ float sh[32*64];
    __shared__ float sbi[64], sbo[64];
    int ntile = blockIdx.x, e = blockIdx.y, b = blockIdx.z;
    int tid = threadIdx.x;

    const float4* wi4 = (const float4*)(Win + e*4096);
    const float4* wo4 = (const float4*)(Wout + e*4096);
    #pragma unroll
    for (int i = 0; i < 4; i++) {
        ((float4*)sWi)[tid + i*256] = wi4[tid + i*256];
        ((float4*)sWo)[tid + i*256] = wo4[tid + i*256];
    }
    const float4* h4 = (const float4*)(g_h + (b*NN + ntile*32)*64);
    #pragma unroll
    for (int i = 0; i < 2; i++) ((float4*)sh)[tid + i*256] = h4[tid + i*256];
    if (tid < 64) { sbi[tid] = bin[e*64 + tid]; sbo[tid] = bout[e*64 + tid]; }
    __syncthreads();

    int col = tid & 63, rg = tid >> 6;
    float* insp = g_ins  + ((b*EE + e)*NN + ntile*32)*64;
    float* outp = g_outs + ((b*EE + e)*NN + ntile*32)*64;
    for (int r = rg; r < 32; r += 4) {
        float ai = sbi[col], ao = sbo[col];
        #pragma unroll
        for (int k = 0; k < 64; k++) {
            float hv = sh[r*64 + k];
            ai += hv * sWi[k*64 + col];
            ao += hv * sWo[k*64 + col];
        }
        insp[r*64 + col] = ai;
        outp[r*64 + col] = ao;
    }
}

// ---------------- big GEMM: a = Adj_half (2048x4096) @ msgs (4096x64) ----------------
// grid (32, 2, B): (row-tile of 64, dir, batch); 256 threads; 4x4 microtile
__global__ void k_bigmm(const float* __restrict__ adj) {
    __shared__ float sA[32*65];   // transposed A tile: sA[k][row], pad 65 (conflict-free)
    __shared__ float sB[32*64];   // sB[k][d]
    int mt = blockIdx.x, dir = blockIdx.y, b = blockIdx.z;
    int tid = threadIdx.x;
    int tx = tid & 15, ty = tid >> 4;

    const float* src = (dir ? g_outs : g_ins) + b*EN*64;
    const float* arow = adj + ((size_t)b*NN + mt*64)*ADJW + dir*EN;

    float acc[4][4] = {};
    for (int k0 = 0; k0 < EN; k0 += 32) {
        #pragma unroll
        for (int i = 0; i < 2; i++) {
            int idx = tid + i*256;
            int rl = idx >> 3, kq = idx & 7;
            float4 v = *(const float4*)(arow + (size_t)rl*ADJW + k0 + kq*4);
            sA[(kq*4+0)*65 + rl] = v.x;
            sA[(kq*4+1)*65 + rl] = v.y;
            sA[(kq*4+2)*65 + rl] = v.z;
            sA[(kq*4+3)*65 + rl] = v.w;
        }
        #pragma unroll
        for (int i = 0; i < 2; i++) {
            int idx = tid + i*256;
            int ml = idx >> 4, dq = idx & 15;
            *(float4*)(sB + ml*64 + dq*4) = *(const float4*)(src + (k0+ml)*64 + dq*4);
        }
        __syncthreads();
        #pragma unroll
        for (int k = 0; k < 32; k++) {
            float4 b4 = *(float4*)(sB + k*64 + tx*4);
            #pragma unroll
            for (int i = 0; i < 4; i++) {
                float a = sA[k*65 + 4*ty + i];
                acc[i][0] += a * b4.x;
                acc[i][1] += a * b4.y;
                acc[i][2] += a * b4.z;
                acc[i][3] += a * b4.w;
            }
        }
        __syncthreads();
    }
    float* dst = (dir ? g_aout : g_ain) + (b*NN + mt*64)*64;
    #pragma unroll
    for (int i = 0; i < 4; i++) {
        float4 v = make_float4(acc[i][0], acc[i][1], acc[i][2], acc[i][3]);
        *(float4*)(dst + (4*ty + i)*64 + tx*4) = v;
    }
}

// ---------------- GRU gate update ----------------
// grid (128, B): 16 rows/block, 256 threads (col = tid&63, each thread: 4 rows)
__global__ void k_gru(const float* __restrict__ Wr, const float* __restrict__ br,
                      const float* __restrict__ Wz, const float* __restrict__ bz,
                      const float* __restrict__ Wh, const float* __restrict__ bh) {
    __shared__ float sa[16*192];
    __shared__ float sj[16*64];
    int nt = blockIdx.x, b = blockIdx.y;
    int tid = threadIdx.x;
    int n0 = nt * 16;

    const float* ain  = g_ain  + (b*NN + n0)*64;
    const float* aout = g_aout + (b*NN + n0)*64;
    const float* hp   = g_h    + (b*NN + n0)*64;
    for (int i = tid; i < 16*64; i += 256) {
        int r = i >> 6, c = i & 63;
        sa[r*192 + c]       = ain[r*64 + c];
        sa[r*192 + 64 + c]  = aout[r*64 + c];
        sa[r*192 + 128 + c] = hp[r*64 + c];
    }
    __syncthreads();

    int col = tid & 63, rg = tid >> 6;
    float accR[4], accZ[4];
    #pragma unroll
    for (int ii = 0; ii < 4; ii++) { accR[ii] = br[col]; accZ[ii] = bz[col]; }
    #pragma unroll 8
    for (int k = 0; k < 192; k++) {
        float wr = Wr[k*64 + col], wz = Wz[k*64 + col];
        #pragma unroll
        for (int ii = 0; ii < 4; ii++) {
            float v = sa[(rg + 4*ii)*192 + k];
            accR[ii] += v * wr;
            accZ[ii] += v * wz;
        }
    }
    float zz[4], hold[4];
    #pragma unroll
    for (int ii = 0; ii < 4; ii++) {
        int r = rg + 4*ii;
        float rr = sigf(accR[ii]);
        zz[ii]  = sigf(accZ[ii]);
        hold[ii] = sa[r*192 + 128 + col];
        sj[r*64 + col] = rr * hold[ii];
    }
    __syncthreads();

    float accH[4];
    #pragma unroll
    for (int ii = 0; ii < 4; ii++) accH[ii] = bh[col];
    #pragma unroll 8
    for (int k = 0; k < 128; k++) {
        float wh = Wh[k*64 + col];
        #pragma unroll
        for (int ii = 0; ii < 4; ii++) accH[ii] += sa[(rg + 4*ii)*192 + k] * wh;
    }
    #pragma unroll 8
    for (int k = 0; k < 64; k++) {
        float wh = Wh[(128 + k)*64 + col];
        #pragma unroll
        for (int ii = 0; ii < 4; ii++) accH[ii] += sj[(rg + 4*ii)*64 + k] * wh;
    }
    float* hw = g_h + (b*NN + n0)*64;
    #pragma unroll
    for (int ii = 0; ii < 4; ii++) {
        int r = rg + 4*ii;
        float hh = tanhf(accH[ii]);
        hw[r*64 + col] = (1.0f - zz[ii]) * hold[ii] + zz[ii] * hh;
    }
}

// ---------------- readout: sum_j sigmoid([h,ann] @ Wo1 + bo1)_j * Wo2_j + bo2 ----------------
// grid 1024 blocks (4 rows each), 128 threads (one hidden unit each)
__global__ void k_out(const float* __restrict__ ann, const float* __restrict__ Wo1,
                      const float* __restrict__ bo1, const float* __restrict__ Wo2,
                      const float* __restrict__ bo2, float* __restrict__ out) {
    __shared__ float sx[4][80];
    __shared__ float sred[128];
    int blk = blockIdx.x;
    int b = blk >> 9;               // 512 blocks per batch
    int n0 = (blk & 511) * 4;
    int tid = threadIdx.x;

    for (int i = tid; i < 4*64; i += 128) {
        int r = i >> 6, c = i & 63;
        sx[r][c] = g_h[(b*NN + n0 + r)*64 + c];
    }
    if (tid < 64) {
        int r = tid >> 4, c = tid & 15;
        sx[r][64 + c] = ann[(b*NN + n0 + r)*AAN + c];
    }
    __syncthreads();

    float v[4];
    float w2 = Wo2[tid];
    float b1 = bo1[tid];
    #pragma unroll
    for (int r = 0; r < 4; r++) {
        float acc = b1;
        #pragma unroll 10
        for (int k = 0; k < 80; k++) acc += sx[r][k] * Wo1[k*128 + tid];
        v[r] = w2 * sigf(acc);
    }
    #pragma unroll
    for (int r = 0; r < 4; r++) {
        sred[tid] = v[r];
        __syncthreads();
        for (int s = 64; s > 0; s >>= 1) {
            if (tid < s) sred[tid] += sred[tid + s];
            __syncthreads();
        }
        if (tid == 0) out[b*NN + n0 + r] = sred[0] + bo2[0];
        __syncthreads();
    }
}

extern "C" void kernel_launch(void* const* d_in, const int* in_sizes, int n_in,
                              void* d_out, int out_size) {
    const float* prop = (const float*)d_in[0];
    const float* ann  = (const float*)d_in[1];
    const float* adj  = (const float*)d_in[2];
    const float* Win  = (const float*)d_in[3];
    const float* bin  = (const float*)d_in[4];
    const float* Wout = (const float*)d_in[5];
    const float* bout = (const float*)d_in[6];
    const float* Wr   = (const float*)d_in[7];
    const float* br   = (const float*)d_in[8];
    const float* Wz   = (const float*)d_in[9];
    const float* bz   = (const float*)d_in[10];
    const float* Wh   = (const float*)d_in[11];
    const float* bh   = (const float*)d_in[12];
    const float* Wo1  = (const float*)d_in[13];
    const float* bo1  = (const float*)d_in[14];
    const float* Wo2  = (const float*)d_in[15];
    const float* bo2  = (const float*)d_in[16];
    float* out = (float*)d_out;

    k_init<<<256, 256>>>((const float4*)prop);
    for (int t = 0; t < TT; t++) {
        k_transform<<<dim3(64, EE, BB), 256>>>(Win, bin, Wout, bout);
        k_bigmm<<<dim3(32, 2, BB), 256>>>(adj);
        k_gru<<<dim3(128, BB), 256>>>(Wr, br, Wz, bz, Wh, bh);
    }
    k_out<<<1024, 128>>>(ann, Wo1, bo1, Wo2, bo2, out);
}

// round 4
// speedup vs baseline: 3.0846x; 3.0761x over previous
#include <cuda_runtime.h>
#include <cstdint>

#define BB 2
#define NN 2048
#define DD 64
#define AAN 16
#define EE 2
#define TT 5
#define HH 128
#define EN (EE*NN)       /* 4096 */
#define ADJW (2*EN)      /* 8192 */

// ---------------- device scratch (no allocation allowed) ----------------
__device__ float g_adjR[(size_t)BB*NN*ADJW];   // adj RN-rounded to tf32
__device__ float g_h[BB*NN*DD];
__device__ float g_msgT[2*BB*DD*EN];           // [dir][b][d][m], m = e*NN+n, tf32-rounded
__device__ float g_ain[BB*NN*DD];
__device__ float g_aout[BB*NN*DD];

__device__ __forceinline__ float sigf(float x){ return 1.0f/(1.0f+__expf(-x)); }
__device__ __forceinline__ float tf32r(float x){ float y; asm("cvt.rn.tf32.f32 %0, %1;":"=f"(y):"f"(x)); return y; }
__device__ __forceinline__ uint32_t s2u(const void* p){
    uint32_t a; asm("{ .reg .u64 t; cvta.to.shared.u64 t, %1; cvt.u32.u64 %0, t; }":"=r"(a):"l"(p)); return a;
}
__device__ __forceinline__ void cpa16(uint32_t d, const void* s){
    asm volatile("cp.async.cg.shared.global [%0], [%1], 16;"::"r"(d),"l"(s));
}
#define CPCOMMIT() asm volatile("cp.async.commit_group;":::"memory")
#define CPWAIT(n)  asm volatile("cp.async.wait_group %0;"::"n"(n):"memory")

// tf32 tensor-core MMA (legal at compute_103 base target)
__device__ __forceinline__ void mma8(float* c, uint32_t a0, uint32_t a1, uint32_t a2, uint32_t a3,
                                     uint32_t b0, uint32_t b1){
    asm volatile("mma.sync.aligned.m16n8k8.row.col.f32.tf32.tf32.f32 "
                 "{%0,%1,%2,%3},{%4,%5,%6,%7},{%8,%9},{%0,%1,%2,%3};"
                 : "+f"(c[0]),"+f"(c[1]),"+f"(c[2]),"+f"(c[3])
                 : "r"(a0),"r"(a1),"r"(a2),"r"(a3),"r"(b0),"r"(b1));
}

// ---------------- init / round ----------------
__global__ void k_init(const float4* __restrict__ ps) {
    int i = blockIdx.x*256 + threadIdx.x;
    ((float4*)g_h)[i] = ps[i];
}
__global__ void k_round(const float4* __restrict__ adj) {
    int i0 = blockIdx.x*1024 + threadIdx.x;
    float4* dst = (float4*)g_adjR;
    #pragma unroll
    for (int j = 0; j < 4; j++) {
        float4 v = adj[i0 + j*256];
        v.x = tf32r(v.x); v.y = tf32r(v.y); v.z = tf32r(v.z); v.w = tf32r(v.w);
        dst[i0 + j*256] = v;
    }
}

// ---------------- transform: msgT[io][b][d][e*2048+n] = tf32( h@W_io[e] + b_io[e] ) ----------------
__global__ void k_transform(const float* __restrict__ Win, const float* __restrict__ bin,
                            const float* __restrict__ Wout, const float* __restrict__ bout) {
    __shared__ float sh[32*64];
    __shared__ float sWi[64*64], sWo[64*64];
    __shared__ float sT[64*33];
    __shared__ float sbi[64], sbo[64];
    int nt = blockIdx.x, e = blockIdx.y, b = blockIdx.z;
    int tid = threadIdx.x;

    const float4* h4 = (const float4*)(g_h + (b*NN + nt*32)*64);
    #pragma unroll
    for (int i = 0; i < 2; i++) ((float4*)sh)[tid + i*256] = h4[tid + i*256];
    const float4* wi4 = (const float4*)(Win + e*4096);
    const float4* wo4 = (const float4*)(Wout + e*4096);
    #pragma unroll
    for (int i = 0; i < 4; i++) {
        ((float4*)sWi)[tid + i*256] = wi4[tid + i*256];
        ((float4*)sWo)[tid + i*256] = wo4[tid + i*256];
    }
    if (tid < 64) { sbi[tid] = bin[e*64 + tid]; sbo[tid] = bout[e*64 + tid]; }
    __syncthreads();

    int col = tid & 63, rg = tid >> 6;
    for (int io = 0; io < 2; io++) {
        if (io) __syncthreads();
        const float* w = io ? sWo : sWi;
        const float* bb = io ? sbo : sbi;
        #pragma unroll
        for (int ii = 0; ii < 8; ii++) {
            int r = rg + 4*ii;
            float acc = bb[col];
            #pragma unroll
            for (int k = 0; k < 64; k++) acc += sh[r*64 + k] * w[k*64 + col];
            sT[col*33 + r] = acc;
        }
        __syncthreads();
        float* dst = g_msgT + ((size_t)(io*BB + b))*(DD*(size_t)EN) + e*NN + nt*32;
        #pragma unroll
        for (int i = 0; i < 8; i++) {
            int idx = tid + i*256;
            int d = idx >> 5, n = idx & 31;
            dst[(size_t)d*EN + n] = tf32r(sT[d*33 + n]);
        }
    }
}

// ---------------- GEMM: C[2048x64] = AdjR_dir[2048x4096] @ msg[4096x64] via mma.sync tf32 ----------------
// grid (32 mtiles, 2 dir, 2 b), 128 threads (4 warps, 32x32 warp tiles), K-chunk 32, 4 stages
#define KCH 128
#define STG_F 4608                 /* floats per stage: A 64*36 + B 64*36 */
#define SMEM_GEMM (4*STG_F*4)      /* 73728 B */

__global__ __launch_bounds__(128, 1) void k_gemm() {
    extern __shared__ float smf[];
    uint32_t usm = s2u(smf);
    int tid = threadIdx.x;
    int wid = tid >> 5, lane = tid & 31;
    int lr = lane >> 2, lc = lane & 3;
    int wm = wid & 1, wn = wid >> 1;
    int mt = blockIdx.x, dir = blockIdx.y, b = blockIdx.z;
    int m0 = mt * 64;

    const float* aBase = g_adjR + ((size_t)(b*NN + m0))*ADJW + (size_t)dir*EN;
    const float* bBase = g_msgT + ((size_t)(dir*BB + b))*(DD*(size_t)EN);

    // fill one stage: A 64x32 (row stride 36f) + B 64x32 (rows = d)
    auto fill = [&](int stage, int c) {
        uint32_t ab = usm + stage*STG_F*4;
        uint32_t bbsu = ab + 2304*4;
        const float* as = aBase + c*32;
        const float* bs = bBase + c*32;
        #pragma unroll
        for (int i = 0; i < 4; i++) {
            int idx = tid + i*128;
            int r = idx >> 3, q = idx & 7;
            cpa16(ab + (r*36 + q*4)*4, as + (size_t)r*ADJW + q*4);
        }
        #pragma unroll
        for (int i = 0; i < 4; i++) {
            int idx = tid + i*128;
            int r = idx >> 3, q = idx & 7;
            cpa16(bbsu + (r*36 + q*4)*4, bs + (size_t)r*EN + q*4);
        }
        CPCOMMIT();
    };

    for (int s = 0; s < 3; s++) fill(s, s);

    float acc[2][4][4];
    #pragma unroll
    for (int i = 0; i < 2; i++)
        #pragma unroll
        for (int j = 0; j < 4; j++)
            #pragma unroll
            for (int q = 0; q < 4; q++) acc[i][j][q] = 0.f;

    for (int c = 0; c < KCH; c++) {
        int st = c & 3;
        if (c < KCH-2) CPWAIT(2); else if (c == KCH-2) CPWAIT(1); else CPWAIT(0);
        __syncthreads();
        if (c + 3 < KCH) fill((c+3) & 3, c+3);

        const uint32_t* sa32 = (const uint32_t*)(smf + st*STG_F);
        const uint32_t* sb32 = sa32 + 2304;
        #pragma unroll
        for (int ks = 0; ks < 4; ks++) {
            int k0 = ks*8 + lc;
            uint32_t afr[2][4];
            #pragma unroll
            for (int mf = 0; mf < 2; mf++) {
                int base = (wm*32 + mf*16 + lr)*36 + k0;
                afr[mf][0] = sa32[base];
                afr[mf][1] = sa32[base + 8*36];
                afr[mf][2] = sa32[base + 4];
                afr[mf][3] = sa32[base + 8*36 + 4];
            }
            uint32_t bfr[4][2];
            #pragma unroll
            for (int nf = 0; nf < 4; nf++) {
                int nb = (wn*32 + nf*8 + lr)*36 + k0;
                bfr[nf][0] = sb32[nb];
                bfr[nf][1] = sb32[nb + 4];
            }
            #pragma unroll
            for (int mf = 0; mf < 2; mf++)
                #pragma unroll
                for (int nf = 0; nf < 4; nf++)
                    mma8(acc[mf][nf], afr[mf][0], afr[mf][1], afr[mf][2], afr[mf][3],
                         bfr[nf][0], bfr[nf][1]);
        }
    }

    float* dst = (dir ? g_aout : g_ain) + (size_t)b*NN*64;
    #pragma unroll
    for (int mf = 0; mf < 2; mf++) {
        #pragma unroll
        for (int nf = 0; nf < 4; nf++) {
            int row = m0 + wm*32 + mf*16 + lr;
            int colg = wn*32 + nf*8 + lc*2;
            float2 v01 = make_float2(acc[mf][nf][0], acc[mf][nf][1]);
            float2 v23 = make_float2(acc[mf][nf][2], acc[mf][nf][3]);
            *(float2*)(dst + (size_t)row*64 + colg) = v01;
            *(float2*)(dst + (size_t)(row+8)*64 + colg) = v23;
        }
    }
}

// ---------------- GRU: weights fully smem-staged; 512 thr, 32 rows/block ----------------
#define GRU_WR 0
#define GRU_WZ 12288
#define GRU_WH 24576
#define GRU_SA 36864              /* 32*192 */
#define GRU_RH 43008              /* 32*64  */
#define SMEM_GRU ((GRU_RH + 2048)*4)   /* 180224 B */

__global__ __launch_bounds__(512, 1) void k_gru(
        const float* __restrict__ Wr, const float* __restrict__ br,
        const float* __restrict__ Wz, const float* __restrict__ bz,
        const float* __restrict__ Wh, const float* __restrict__ bh) {
    extern __shared__ float smf[];
    int nt = blockIdx.x, b = blockIdx.y;
    int tid = threadIdx.x;
    int n0 = nt * 32;

    #pragma unroll
    for (int i = 0; i < 6; i++) {
        int idx = tid + i*512;      // 3072 float4 per weight
        ((float4*)(smf + GRU_WR))[idx] = ((const float4*)Wr)[idx];
        ((float4*)(smf + GRU_WZ))[idx] = ((const float4*)Wz)[idx];
        ((float4*)(smf + GRU_WH))[idx] = ((const float4*)Wh)[idx];
    }
    const float* ain  = g_ain  + (size_t)(b*NN + n0)*64;
    const float* aout = g_aout + (size_t)(b*NN + n0)*64;
    const float* hp   = g_h    + (size_t)(b*NN + n0)*64;
    #pragma unroll
    for (int i = 0; i < 4; i++) {
        int idx = tid + i*512;      // 2048 elems
        int r = idx >> 6, c = idx & 63;
        smf[GRU_SA + r*192 + c]       = ain[r*64 + c];
        smf[GRU_SA + r*192 + 64 + c]  = aout[r*64 + c];
        smf[GRU_SA + r*192 + 128 + c] = hp[r*64 + c];
    }
    __syncthreads();

    int col = tid & 63, rg = tid >> 6;        // 8 row-groups, 4 rows each
    const float* sa = smf + GRU_SA;
    float accR[4], accZ[4];
    #pragma unroll
    for (int i = 0; i < 4; i++) { accR[i] = br[col]; accZ[i] = bz[col]; }
    #pragma unroll 8
    for (int k = 0; k < 192; k++) {
        float wr = smf[GRU_WR + k*64 + col];
        float wz = smf[GRU_WZ + k*64 + col];
        #pragma unroll
        for (int i = 0; i < 4; i++) {
            float v = sa[(rg*4 + i)*192 + k];
            accR[i] += v*wr; accZ[i] += v*wz;
        }
    }
    float zg[4], hold[4];
    #pragma unroll
    for (int i = 0; i < 4; i++) {
        int r = rg*4 + i;
        float rr = sigf(accR[i]);
        zg[i] = sigf(accZ[i]);
        hold[i] = sa[r*192 + 128 + col];
        smf[GRU_RH + r*64 + col] = rr * hold[i];
    }
    __syncthreads();

    float accH[4];
    #pragma unroll
    for (int i = 0; i < 4; i++) accH[i] = bh[col];
    #pragma unroll 8
    for (int k = 0; k < 128; k++) {
        float wh = smf[GRU_WH + k*64 + col];
        #pragma unroll
        for (int i = 0; i < 4; i++) accH[i] += sa[(rg*4 + i)*192 + k]*wh;
    }
    #pragma unroll 8
    for (int k = 0; k < 64; k++) {
        float wh = smf[GRU_WH + (128 + k)*64 + col];
        #pragma unroll
        for (int i = 0; i < 4; i++) accH[i] += smf[GRU_RH + (rg*4 + i)*64 + k]*wh;
    }
    float* hw = g_h + (size_t)(b*NN + n0)*64;
    #pragma unroll
    for (int i = 0; i < 4; i++) {
        int r = rg*4 + i;
        float hh = tanhf(accH[i]);
        hw[r*64 + col] = (1.0f - zg[i])*hold[i] + zg[i]*hh;
    }
}

// ---------------- readout ----------------
__global__ void k_out(const float* __restrict__ ann, const float* __restrict__ Wo1,
                      const float* __restrict__ bo1, const float* __restrict__ Wo2,
                      const float* __restrict__ bo2, float* __restrict__ out) {
    __shared__ float sx[4][80];
    __shared__ float sred[128];
    int blk = blockIdx.x;
    int b = blk >> 9;
    int n0 = (blk & 511) * 4;
    int tid = threadIdx.x;
    for (int i = tid; i < 256; i += 128) {
        int r = i >> 6, c = i & 63;
        sx[r][c] = g_h[(b*NN + n0 + r)*64 + c];
    }
    if (tid < 64) {
        int r = tid >> 4, c = tid & 15;
        sx[r][64 + c] = ann[(b*NN + n0 + r)*AAN + c];
    }
    __syncthreads();
    float v[4];
    float w2 = Wo2[tid], b1 = bo1[tid];
    #pragma unroll
    for (int r = 0; r < 4; r++) {
        float acc = b1;
        #pragma unroll 10
        for (int k = 0; k < 80; k++) acc += sx[r][k]*Wo1[k*128 + tid];
        v[r] = w2 * sigf(acc);
    }
    #pragma unroll
    for (int r = 0; r < 4; r++) {
        sred[tid] = v[r];
        __syncthreads();
        for (int s = 64; s > 0; s >>= 1) {
            if (tid < s) sred[tid] += sred[tid + s];
            __syncthreads();
        }
        if (tid == 0) out[b*NN + n0 + r] = sred[0] + bo2[0];
        __syncthreads();
    }
}

extern "C" void kernel_launch(void* const* d_in, const int* in_sizes, int n_in,
                              void* d_out, int out_size) {
    const float* prop = (const float*)d_in[0];
    const float* ann  = (const float*)d_in[1];
    const float* adj  = (const float*)d_in[2];
    const float* Win  = (const float*)d_in[3];
    const float* bin  = (const float*)d_in[4];
    const float* Wout = (const float*)d_in[5];
    const float* bout = (const float*)d_in[6];
    const float* Wr   = (const float*)d_in[7];
    const float* br   = (const float*)d_in[8];
    const float* Wz   = (const float*)d_in[9];
    const float* bz   = (const float*)d_in[10];
    const float* Wh   = (const float*)d_in[11];
    const float* bh   = (const float*)d_in[12];
    const float* Wo1  = (const float*)d_in[13];
    const float* bo1  = (const float*)d_in[14];
    const float* Wo2  = (const float*)d_in[15];
    const float* bo2  = (const float*)d_in[16];
    float* out = (float*)d_out;

    cudaFuncSetAttribute(k_gemm, cudaFuncAttributeMaxDynamicSharedMemorySize, SMEM_GEMM);
    cudaFuncSetAttribute(k_gru,  cudaFuncAttributeMaxDynamicSharedMemorySize, SMEM_GRU);

    k_init<<<256, 256>>>((const float4*)prop);
    k_round<<<8192, 256>>>((const float4*)adj);
    for (int t = 0; t < TT; t++) {
        k_transform<<<dim3(64, EE, BB), 256>>>(Win, bin, Wout, bout);
        k_gemm<<<dim3(32, 2, BB), 128, SMEM_GEMM>>>();
        k_gru<<<dim3(64, BB), 512, SMEM_GRU>>>(Wr, br, Wz, bz, Wh, bh);
    }
    k_out<<<1024, 128>>>(ann, Wo1, bo1, Wo2, bo2, out);
}

// round 5
// speedup vs baseline: 3.5378x; 1.1469x over previous
#include <cuda_runtime.h>
#include <cstdint>

#define BB 2
#define NN 2048
#define DD 64
#define AAN 16
#define EE 2
#define TT 5
#define HH 128
#define EN (EE*NN)       /* 4096 */
#define ADJW (2*EN)      /* 8192 */
#define KSPL 2
#define KCH 64           /* 32-wide K chunks per split: 2048/32 */

// ---------------- device scratch (no allocation allowed) ----------------
__device__ float g_adjR[(size_t)BB*NN*ADJW];       // adj RN-rounded to tf32
__device__ float g_h[BB*NN*DD];
__device__ float g_msgT[2*BB*DD*EN];               // [dir][b][d][m], tf32-rounded
__device__ float g_ain[KSPL*BB*NN*DD];             // K-split partials
__device__ float g_aout[KSPL*BB*NN*DD];

__device__ __forceinline__ float sigf(float x){ return 1.0f/(1.0f+__expf(-x)); }
__device__ __forceinline__ float tf32r(float x){ float y; asm("cvt.rn.tf32.f32 %0, %1;":"=f"(y):"f"(x)); return y; }
__device__ __forceinline__ uint32_t s2u(const void* p){
    uint32_t a; asm("{ .reg .u64 t; cvta.to.shared.u64 t, %1; cvt.u32.u64 %0, t; }":"=r"(a):"l"(p)); return a;
}
__device__ __forceinline__ void cpa16(uint32_t d, const void* s){
    asm volatile("cp.async.cg.shared.global [%0], [%1], 16;"::"r"(d),"l"(s));
}
#define CPCOMMIT() asm volatile("cp.async.commit_group;":::"memory")
#define CPWAIT(n)  asm volatile("cp.async.wait_group %0;"::"n"(n):"memory")

__device__ __forceinline__ void mma8(float* c, uint32_t a0, uint32_t a1, uint32_t a2, uint32_t a3,
                                     uint32_t b0, uint32_t b1){
    asm volatile("mma.sync.aligned.m16n8k8.row.col.f32.tf32.tf32.f32 "
                 "{%0,%1,%2,%3},{%4,%5,%6,%7},{%8,%9},{%0,%1,%2,%3};"
                 : "+f"(c[0]),"+f"(c[1]),"+f"(c[2]),"+f"(c[3])
                 : "r"(a0),"r"(a1),"r"(a2),"r"(a3),"r"(b0),"r"(b1));
}

// ---------------- init / round ----------------
__global__ void k_init(const float4* __restrict__ ps) {
    int i = blockIdx.x*256 + threadIdx.x;
    ((float4*)g_h)[i] = ps[i];
}
__global__ void k_round(const float4* __restrict__ adj) {
    int i0 = blockIdx.x*1024 + threadIdx.x;
    float4* dst = (float4*)g_adjR;
    #pragma unroll
    for (int j = 0; j < 4; j++) {
        float4 v = adj[i0 + j*256];
        v.x = tf32r(v.x); v.y = tf32r(v.y); v.z = tf32r(v.z); v.w = tf32r(v.w);
        dst[i0 + j*256] = v;
    }
}

// ---------------- transform: msgT[io][b][d][e*2048+n] = tf32( h@W_io[e] + b_io[e] ) ----------------
__global__ void k_transform(const float* __restrict__ Win, const float* __restrict__ bin,
                            const float* __restrict__ Wout, const float* __restrict__ bout) {
    __shared__ float sh[32*64];
    __shared__ float sWi[64*64], sWo[64*64];
    __shared__ float sT[64*33];
    __shared__ float sbi[64], sbo[64];
    int nt = blockIdx.x, e = blockIdx.y, b = blockIdx.z;
    int tid = threadIdx.x;

    const float4* h4 = (const float4*)(g_h + (b*NN + nt*32)*64);
    #pragma unroll
    for (int i = 0; i < 2; i++) ((float4*)sh)[tid + i*256] = h4[tid + i*256];
    const float4* wi4 = (const float4*)(Win + e*4096);
    const float4* wo4 = (const float4*)(Wout + e*4096);
    #pragma unroll
    for (int i = 0; i < 4; i++) {
        ((float4*)sWi)[tid + i*256] = wi4[tid + i*256];
        ((float4*)sWo)[tid + i*256] = wo4[tid + i*256];
    }
    if (tid < 64) { sbi[tid] = bin[e*64 + tid]; sbo[tid] = bout[e*64 + tid]; }
    __syncthreads();

    int col = tid & 63, rg = tid >> 6;
    for (int io = 0; io < 2; io++) {
        if (io) __syncthreads();
        const float* w = io ? sWo : sWi;
        const float* bb = io ? sbo : sbi;
        #pragma unroll
        for (int ii = 0; ii < 8; ii++) {
            int r = rg + 4*ii;
            float acc = bb[col];
            #pragma unroll
            for (int k = 0; k < 64; k++) acc += sh[r*64 + k] * w[k*64 + col];
            sT[col*33 + r] = acc;
        }
        __syncthreads();
        float* dst = g_msgT + ((size_t)(io*BB + b))*(DD*(size_t)EN) + e*NN + nt*32;
        #pragma unroll
        for (int i = 0; i < 8; i++) {
            int idx = tid + i*256;
            int d = idx >> 5, n = idx & 31;
            dst[(size_t)d*EN + n] = tf32r(sT[d*33 + n]);
        }
    }
}

// ---------------- GEMM (K-split): Cpart = AdjR[64 x 2048] @ msg[2048 x 64] ----------------
// grid (32 mtiles, 2 dir, BB*KSPL), 128 threads, 4 warps of 32x32, 4 stages
#define STG_F 4608                 /* A 64*36 + B 64*36 floats */
#define SMEM_GEMM (4*STG_F*4)      /* 73728 B */

__global__ __launch_bounds__(128, 2) void k_gemm() {
    extern __shared__ float smf[];
    uint32_t usm = s2u(smf);
    int tid = threadIdx.x;
    int wid = tid >> 5, lane = tid & 31;
    int lr = lane >> 2, lc = lane & 3;
    int wm = wid & 1, wn = wid >> 1;
    int mt = blockIdx.x, dir = blockIdx.y;
    int b = blockIdx.z >> 1, ks = blockIdx.z & 1;
    int m0 = mt * 64;

    const float* aBase = g_adjR + ((size_t)(b*NN + m0))*ADJW + (size_t)dir*EN + ks*2048;
    const float* bBase = g_msgT + ((size_t)(dir*BB + b))*(DD*(size_t)EN) + ks*2048;

    auto fill = [&](int stage, int c) {
        uint32_t ab = usm + stage*STG_F*4;
        uint32_t bbsu = ab + 2304*4;
        const float* as = aBase + c*32;
        const float* bs = bBase + c*32;
        #pragma unroll
        for (int i = 0; i < 4; i++) {
            int idx = tid + i*128;
            int r = idx >> 3, q = idx & 7;
            cpa16(ab + (r*36 + q*4)*4, as + (size_t)r*ADJW + q*4);
        }
        #pragma unroll
        for (int i = 0; i < 4; i++) {
            int idx = tid + i*128;
            int r = idx >> 3, q = idx & 7;
            cpa16(bbsu + (r*36 + q*4)*4, bs + (size_t)r*EN + q*4);
        }
        CPCOMMIT();
    };

    for (int s = 0; s < 3; s++) fill(s, s);

    float acc[2][4][4];
    #pragma unroll
    for (int i = 0; i < 2; i++)
        #pragma unroll
        for (int j = 0; j < 4; j++)
            #pragma unroll
            for (int q = 0; q < 4; q++) acc[i][j][q] = 0.f;

    for (int c = 0; c < KCH; c++) {
        int st = c & 3;
        if (c < KCH-2) CPWAIT(2); else if (c == KCH-2) CPWAIT(1); else CPWAIT(0);
        __syncthreads();
        if (c + 3 < KCH) fill((c+3) & 3, c+3);

        const uint32_t* sa32 = (const uint32_t*)(smf + st*STG_F);
        const uint32_t* sb32 = sa32 + 2304;
        #pragma unroll
        for (int kss = 0; kss < 4; kss++) {
            int k0 = kss*8 + lc;
            uint32_t afr[2][4];
            #pragma unroll
            for (int mf = 0; mf < 2; mf++) {
                int base = (wm*32 + mf*16 + lr)*36 + k0;
                afr[mf][0] = sa32[base];
                afr[mf][1] = sa32[base + 8*36];
                afr[mf][2] = sa32[base + 4];
                afr[mf][3] = sa32[base + 8*36 + 4];
            }
            uint32_t bfr[4][2];
            #pragma unroll
            for (int nf = 0; nf < 4; nf++) {
                int nb = (wn*32 + nf*8 + lr)*36 + k0;
                bfr[nf][0] = sb32[nb];
                bfr[nf][1] = sb32[nb + 4];
            }
            #pragma unroll
            for (int mf = 0; mf < 2; mf++)
                #pragma unroll
                for (int nf = 0; nf < 4; nf++)
                    mma8(acc[mf][nf], afr[mf][0], afr[mf][1], afr[mf][2], afr[mf][3],
                         bfr[nf][0], bfr[nf][1]);
        }
    }

    float* dst = (dir ? g_aout : g_ain) + (size_t)ks*BB*NN*DD + (size_t)b*NN*64;
    #pragma unroll
    for (int mf = 0; mf < 2; mf++) {
        #pragma unroll
        for (int nf = 0; nf < 4; nf++) {
            int row = m0 + wm*32 + mf*16 + lr;
            int colg = wn*32 + nf*8 + lc*2;
            float2 v01 = make_float2(acc[mf][nf][0], acc[mf][nf][1]);
            float2 v23 = make_float2(acc[mf][nf][2], acc[mf][nf][3]);
            *(float2*)(dst + (size_t)row*64 + colg) = v01;
            *(float2*)(dst + (size_t)(row+8)*64 + colg) = v23;
        }
    }
}

// ---------------- GRU: weights smem-staged; sums the two K-split partials ----------------
#define GRU_WR 0
#define GRU_WZ 12288
#define GRU_WH 24576
#define GRU_SA 36864              /* 32*192 */
#define GRU_RH 43008              /* 32*64  */
#define SMEM_GRU ((GRU_RH + 2048)*4)   /* 180224 B */

__global__ __launch_bounds__(512, 1) void k_gru(
        const float* __restrict__ Wr, const float* __restrict__ br,
        const float* __restrict__ Wz, const float* __restrict__ bz,
        const float* __restrict__ Wh, const float* __restrict__ bh) {
    extern __shared__ float smf[];
    int nt = blockIdx.x, b = blockIdx.y;
    int tid = threadIdx.x;
    int n0 = nt * 32;

    #pragma unroll
    for (int i = 0; i < 6; i++) {
        int idx = tid + i*512;
        ((float4*)(smf + GRU_WR))[idx] = ((const float4*)Wr)[idx];
        ((float4*)(smf + GRU_WZ))[idx] = ((const float4*)Wz)[idx];
        ((float4*)(smf + GRU_WH))[idx] = ((const float4*)Wh)[idx];
    }
    const float* ain0  = g_ain  + (size_t)(b*NN + n0)*64;
    const float* ain1  = ain0 + (size_t)BB*NN*DD;
    const float* aout0 = g_aout + (size_t)(b*NN + n0)*64;
    const float* aout1 = aout0 + (size_t)BB*NN*DD;
    const float* hp    = g_h    + (size_t)(b*NN + n0)*64;
    #pragma unroll
    for (int i = 0; i < 4; i++) {
        int idx = tid + i*512;
        int r = idx >> 6, c = idx & 63;
        smf[GRU_SA + r*192 + c]       = ain0[r*64 + c] + ain1[r*64 + c];
        smf[GRU_SA + r*192 + 64 + c]  = aout0[r*64 + c] + aout1[r*64 + c];
        smf[GRU_SA + r*192 + 128 + c] = hp[r*64 + c];
    }
    __syncthreads();

    int col = tid & 63, rg = tid >> 6;
    const float* sa = smf + GRU_SA;
    float accR[4], accZ[4];
    #pragma unroll
    for (int i = 0; i < 4; i++) { accR[i] = br[col]; accZ[i] = bz[col]; }
    #pragma unroll 8
    for (int k = 0; k < 192; k++) {
        float wr = smf[GRU_WR + k*64 + col];
        float wz = smf[GRU_WZ + k*64 + col];
        #pragma unroll
        for (int i = 0; i < 4; i++) {
            float v = sa[(rg*4 + i)*192 + k];
            accR[i] += v*wr; accZ[i] += v*wz;
        }
    }
    float zg[4], hold[4];
    #pragma unroll
    for (int i = 0; i < 4; i++) {
        int r = rg*4 + i;
        float rr = sigf(accR[i]);
        zg[i] = sigf(accZ[i]);
        hold[i] = sa[r*192 + 128 + col];
        smf[GRU_RH + r*64 + col] = rr * hold[i];
    }
    __syncthreads();

    float accH[4];
    #pragma unroll
    for (int i = 0; i < 4; i++) accH[i] = bh[col];
    #pragma unroll 8
    for (int k = 0; k < 128; k++) {
        float wh = smf[GRU_WH + k*64 + col];
        #pragma unroll
        for (int i = 0; i < 4; i++) accH[i] += sa[(rg*4 + i)*192 + k]*wh;
    }
    #pragma unroll 8
    for (int k = 0; k < 64; k++) {
        float wh = smf[GRU_WH + (128 + k)*64 + col];
        #pragma unroll
        for (int i = 0; i < 4; i++) accH[i] += smf[GRU_RH + (rg*4 + i)*64 + k]*wh;
    }
    float* hw = g_h + (size_t)(b*NN + n0)*64;
    #pragma unroll
    for (int i = 0; i < 4; i++) {
        int r = rg*4 + i;
        float hh = tanhf(accH[i]);
        hw[r*64 + col] = (1.0f - zg[i])*hold[i] + zg[i]*hh;
    }
}

// ---------------- readout ----------------
__global__ void k_out(const float* __restrict__ ann, const float* __restrict__ Wo1,
                      const float* __restrict__ bo1, const float* __restrict__ Wo2,
                      const float* __restrict__ bo2, float* __restrict__ out) {
    __shared__ float sx[4][80];
    __shared__ float sred[128];
    int blk = blockIdx.x;
    int b = blk >> 9;
    int n0 = (blk & 511) * 4;
    int tid = threadIdx.x;
    for (int i = tid; i < 256; i += 128) {
        int r = i >> 6, c = i & 63;
        sx[r][c] = g_h[(b*NN + n0 + r)*64 + c];
    }
    if (tid < 64) {
        int r = tid >> 4, c = tid & 15;
        sx[r][64 + c] = ann[(b*NN + n0 + r)*AAN + c];
    }
    __syncthreads();
    float v[4];
    float w2 = Wo2[tid], b1 = bo1[tid];
    #pragma unroll
    for (int r = 0; r < 4; r++) {
        float acc = b1;
        #pragma unroll 10
        for (int k = 0; k < 80; k++) acc += sx[r][k]*Wo1[k*128 + tid];
        v[r] = w2 * sigf(acc);
    }
    #pragma unroll
    for (int r = 0; r < 4; r++) {
        sred[tid] = v[r];
        __syncthreads();
        for (int s = 64; s > 0; s >>= 1) {
            if (tid < s) sred[tid] += sred[tid + s];
            __syncthreads();
        }
        if (tid == 0) out[b*NN + n0 + r] = sred[0] + bo2[0];
        __syncthreads();
    }
}

extern "C" void kernel_launch(void* const* d_in, const int* in_sizes, int n_in,
                              void* d_out, int out_size) {
    const float* prop = (const float*)d_in[0];
    const float* ann  = (const float*)d_in[1];
    const float* adj  = (const float*)d_in[2];
    const float* Win  = (const float*)d_in[3];
    const float* bin  = (const float*)d_in[4];
    const float* Wout = (const float*)d_in[5];
    const float* bout = (const float*)d_in[6];
    const float* Wr   = (const float*)d_in[7];
    const float* br   = (const float*)d_in[8];
    const float* Wz   = (const float*)d_in[9];
    const float* bz   = (const float*)d_in[10];
    const float* Wh   = (const float*)d_in[11];
    const float* bh   = (const float*)d_in[12];
    const float* Wo1  = (const float*)d_in[13];
    const float* bo1  = (const float*)d_in[14];
    const float* Wo2  = (const float*)d_in[15];
    const float* bo2  = (const float*)d_in[16];
    float* out = (float*)d_out;

    cudaFuncSetAttribute(k_gemm, cudaFuncAttributeMaxDynamicSharedMemorySize, SMEM_GEMM);
    cudaFuncSetAttribute(k_gru,  cudaFuncAttributeMaxDynamicSharedMemorySize, SMEM_GRU);

    k_init<<<256, 256>>>((const float4*)prop);
    k_round<<<8192, 256>>>((const float4*)adj);
    for (int t = 0; t < TT; t++) {
        k_transform<<<dim3(64, EE, BB), 256>>>(Win, bin, Wout, bout);
        k_gemm<<<dim3(32, 2, BB*KSPL), 128, SMEM_GEMM>>>();
        k_gru<<<dim3(64, BB), 512, SMEM_GRU>>>(Wr, br, Wz, bz, Wh, bh);
    }
    k_out<<<1024, 128>>>(ann, Wo1, bo1, Wo2, bo2, out);
}

// round 6
// speedup vs baseline: 3.6272x; 1.0253x over previous
#include <cuda_runtime.h>
#include <cstdint>

#define BB 2
#define NN 2048
#define DD 64
#define AAN 16
#define EE 2
#define TT 5
#define HH 128
#define EN (EE*NN)       /* 4096 */
#define ADJW (2*EN)      /* 8192 */
#define KSPL 4
#define KLEN (EN/KSPL)   /* 1024 */
#define KCH  (KLEN/32)   /* 32 chunks of 32 */

// ---------------- device scratch (no allocation allowed) ----------------
__device__ float g_adjR[(size_t)BB*NN*ADJW];       // adj RN-rounded to tf32
__device__ float g_h[BB*NN*DD];
__device__ float g_msgT[2*BB*DD*EN];               // [dir][b][d][m], tf32-rounded
__device__ float g_ain[KSPL*BB*NN*DD];             // K-split partials
__device__ float g_aout[KSPL*BB*NN*DD];

__device__ __forceinline__ float sigf(float x){ return 1.0f/(1.0f+__expf(-x)); }
__device__ __forceinline__ float tf32r(float x){ float y; asm("cvt.rn.tf32.f32 %0, %1;":"=f"(y):"f"(x)); return y; }
__device__ __forceinline__ uint32_t s2u(const void* p){
    uint32_t a; asm("{ .reg .u64 t; cvta.to.shared.u64 t, %1; cvt.u32.u64 %0, t; }":"=r"(a):"l"(p)); return a;
}
__device__ __forceinline__ void cpa16(uint32_t d, const void* s){
    asm volatile("cp.async.cg.shared.global [%0], [%1], 16;"::"r"(d),"l"(s));
}
#define CPCOMMIT() asm volatile("cp.async.commit_group;":::"memory")
#define CPWAIT(n)  asm volatile("cp.async.wait_group %0;"::"n"(n):"memory")

__device__ __forceinline__ void mma8(float* c, uint32_t a0, uint32_t a1, uint32_t a2, uint32_t a3,
                                     uint32_t b0, uint32_t b1){
    asm volatile("mma.sync.aligned.m16n8k8.row.col.f32.tf32.tf32.f32 "
                 "{%0,%1,%2,%3},{%4,%5,%6,%7},{%8,%9},{%0,%1,%2,%3};"
                 : "+f"(c[0]),"+f"(c[1]),"+f"(c[2]),"+f"(c[3])
                 : "r"(a0),"r"(a1),"r"(a2),"r"(a3),"r"(b0),"r"(b1));
}

// ---------------- init / round ----------------
__global__ void k_init(const float4* __restrict__ ps) {
    int i = blockIdx.x*256 + threadIdx.x;
    ((float4*)g_h)[i] = ps[i];
}
__global__ void k_round(const float4* __restrict__ adj) {
    int i0 = blockIdx.x*1024 + threadIdx.x;
    float4* dst = (float4*)g_adjR;
    #pragma unroll
    for (int j = 0; j < 4; j++) {
        float4 v = adj[i0 + j*256];
        v.x = tf32r(v.x); v.y = tf32r(v.y); v.z = tf32r(v.z); v.w = tf32r(v.w);
        dst[i0 + j*256] = v;
    }
}

// ---------------- transform: msgT[io][b][d][e*2048+n] = tf32( h@W_io[e] + b_io[e] ) ----------------
__global__ void k_transform(const float* __restrict__ Win, const float* __restrict__ bin,
                            const float* __restrict__ Wout, const float* __restrict__ bout) {
    __shared__ float sh[32*64];
    __shared__ float sWi[64*64], sWo[64*64];
    __shared__ float sT[64*33];
    __shared__ float sbi[64], sbo[64];
    int nt = blockIdx.x, e = blockIdx.y, b = blockIdx.z;
    int tid = threadIdx.x;

    const float4* h4 = (const float4*)(g_h + (b*NN + nt*32)*64);
    #pragma unroll
    for (int i = 0; i < 2; i++) ((float4*)sh)[tid + i*256] = h4[tid + i*256];
    const float4* wi4 = (const float4*)(Win + e*4096);
    const float4* wo4 = (const float4*)(Wout + e*4096);
    #pragma unroll
    for (int i = 0; i < 4; i++) {
        ((float4*)sWi)[tid + i*256] = wi4[tid + i*256];
        ((float4*)sWo)[tid + i*256] = wo4[tid + i*256];
    }
    if (tid < 64) { sbi[tid] = bin[e*64 + tid]; sbo[tid] = bout[e*64 + tid]; }
    __syncthreads();

    int col = tid & 63, rg = tid >> 6;
    for (int io = 0; io < 2; io++) {
        if (io) __syncthreads();
        const float* w = io ? sWo : sWi;
        const float* bb = io ? sbo : sbi;
        #pragma unroll
        for (int ii = 0; ii < 8; ii++) {
            int r = rg + 4*ii;
            float acc = bb[col];
            #pragma unroll
            for (int k = 0; k < 64; k++) acc += sh[r*64 + k] * w[k*64 + col];
            sT[col*33 + r] = acc;
        }
        __syncthreads();
        float* dst = g_msgT + ((size_t)(io*BB + b))*(DD*(size_t)EN) + e*NN + nt*32;
        #pragma unroll
        for (int i = 0; i < 8; i++) {
            int idx = tid + i*256;
            int d = idx >> 5, n = idx & 31;
            dst[(size_t)d*EN + n] = tf32r(sT[d*33 + n]);
        }
    }
}

// ---------------- GEMM (K-split x4): Cpart = AdjR[64 x 1024] @ msg[1024 x 64] ----------------
// grid (32 mtiles, 2 dir, BB*KSPL)=512 CTAs, 128 threads, 3 stages, 4 CTAs/SM
#define STG_F 4608                 /* A 64*36 + B 64*36 floats */
#define NSTG 3
#define SMEM_GEMM (NSTG*STG_F*4)   /* 55296 B */

__global__ __launch_bounds__(128, 4) void k_gemm() {
    extern __shared__ float smf[];
    uint32_t usm = s2u(smf);
    int tid = threadIdx.x;
    int wid = tid >> 5, lane = tid & 31;
    int lr = lane >> 2, lc = lane & 3;
    int wm = wid & 1, wn = wid >> 1;
    int mt = blockIdx.x, dir = blockIdx.y;
    int b = blockIdx.z >> 2, ks = blockIdx.z & 3;
    int m0 = mt * 64;

    const float* aBase = g_adjR + ((size_t)(b*NN + m0))*ADJW + (size_t)dir*EN + ks*KLEN;
    const float* bBase = g_msgT + ((size_t)(dir*BB + b))*(DD*(size_t)EN) + ks*KLEN;

    auto fill = [&](int stage, int c) {
        uint32_t ab = usm + stage*STG_F*4;
        uint32_t bbsu = ab + 2304*4;
        const float* as = aBase + c*32;
        const float* bs = bBase + c*32;
        #pragma unroll
        for (int i = 0; i < 4; i++) {
            int idx = tid + i*128;
            int r = idx >> 3, q = idx & 7;
            cpa16(ab + (r*36 + q*4)*4, as + (size_t)r*ADJW + q*4);
        }
        #pragma unroll
        for (int i = 0; i < 4; i++) {
            int idx = tid + i*128;
            int r = idx >> 3, q = idx & 7;
            cpa16(bbsu + (r*36 + q*4)*4, bs + (size_t)r*EN + q*4);
        }
        CPCOMMIT();
    };

    fill(0, 0);
    fill(1, 1);

    float acc[2][4][4];
    #pragma unroll
    for (int i = 0; i < 2; i++)
        #pragma unroll
        for (int j = 0; j < 4; j++)
            #pragma unroll
            for (int q = 0; q < 4; q++) acc[i][j][q] = 0.f;

    int st = 0;
    for (int c = 0; c < KCH; c++) {
        if (c < KCH-1) CPWAIT(1); else CPWAIT(0);
        __syncthreads();
        if (c + 2 < KCH) fill((st + 2 >= NSTG) ? st + 2 - NSTG : st + 2, c + 2);

        const uint32_t* sa32 = (const uint32_t*)(smf + st*STG_F);
        const uint32_t* sb32 = sa32 + 2304;
        #pragma unroll
        for (int kss = 0; kss < 4; kss++) {
            int k0 = kss*8 + lc;
            uint32_t afr[2][4];
            #pragma unroll
            for (int mf = 0; mf < 2; mf++) {
                int base = (wm*32 + mf*16 + lr)*36 + k0;
                afr[mf][0] = sa32[base];
                afr[mf][1] = sa32[base + 8*36];
                afr[mf][2] = sa32[base + 4];
                afr[mf][3] = sa32[base + 8*36 + 4];
            }
            uint32_t bfr[4][2];
            #pragma unroll
            for (int nf = 0; nf < 4; nf++) {
                int nb = (wn*32 + nf*8 + lr)*36 + k0;
                bfr[nf][0] = sb32[nb];
                bfr[nf][1] = sb32[nb + 4];
            }
            #pragma unroll
            for (int mf = 0; mf < 2; mf++)
                #pragma unroll
                for (int nf = 0; nf < 4; nf++)
                    mma8(acc[mf][nf], afr[mf][0], afr[mf][1], afr[mf][2], afr[mf][3],
                         bfr[nf][0], bfr[nf][1]);
        }
        st = (st + 1 >= NSTG) ? 0 : st + 1;
    }

    float* dst = (dir ? g_aout : g_ain) + (size_t)ks*BB*NN*DD + (size_t)b*NN*64;
    #pragma unroll
    for (int mf = 0; mf < 2; mf++) {
        #pragma unroll
        for (int nf = 0; nf < 4; nf++) {
            int row = m0 + wm*32 + mf*16 + lr;
            int colg = wn*32 + nf*8 + lc*2;
            float2 v01 = make_float2(acc[mf][nf][0], acc[mf][nf][1]);
            float2 v23 = make_float2(acc[mf][nf][2], acc[mf][nf][3]);
            *(float2*)(dst + (size_t)row*64 + colg) = v01;
            *(float2*)(dst + (size_t)(row+8)*64 + colg) = v23;
        }
    }
}

// ---------------- GRU: weights smem-staged; sums the four K-split partials ----------------
#define GRU_WR 0
#define GRU_WZ 12288
#define GRU_WH 24576
#define GRU_SA 36864              /* 32*192 */
#define GRU_RH 43008              /* 32*64  */
#define SMEM_GRU ((GRU_RH + 2048)*4)   /* 180224 B */

__global__ __launch_bounds__(512, 1) void k_gru(
        const float* __restrict__ Wr, const float* __restrict__ br,
        const float* __restrict__ Wz, const float* __restrict__ bz,
        const float* __restrict__ Wh, const float* __restrict__ bh) {
    extern __shared__ float smf[];
    int nt = blockIdx.x, b = blockIdx.y;
    int tid = threadIdx.x;
    int n0 = nt * 32;

    #pragma unroll
    for (int i = 0; i < 6; i++) {
        int idx = tid + i*512;
        ((float4*)(smf + GRU_WR))[idx] = ((const float4*)Wr)[idx];
        ((float4*)(smf + GRU_WZ))[idx] = ((const float4*)Wz)[idx];
        ((float4*)(smf + GRU_WH))[idx] = ((const float4*)Wh)[idx];
    }
    const float* ain0  = g_ain  + (size_t)(b*NN + n0)*64;
    const float* aout0 = g_aout + (size_t)(b*NN + n0)*64;
    const float* hp    = g_h    + (size_t)(b*NN + n0)*64;
    const size_t PSTR = (size_t)BB*NN*DD;
    #pragma unroll
    for (int i = 0; i < 4; i++) {
        int idx = tid + i*512;
        int r = idx >> 6, c = idx & 63;
        float si = 0.f, so = 0.f;
        #pragma unroll
        for (int p = 0; p < KSPL; p++) {
            si += ain0[p*PSTR + r*64 + c];
            so += aout0[p*PSTR + r*64 + c];
        }
        smf[GRU_SA + r*192 + c]       = si;
        smf[GRU_SA + r*192 + 64 + c]  = so;
        smf[GRU_SA + r*192 + 128 + c] = hp[r*64 + c];
    }
    __syncthreads();

    int col = tid & 63, rg = tid >> 6;
    const float* sa = smf + GRU_SA;
    float accR[4], accZ[4];
    #pragma unroll
    for (int i = 0; i < 4; i++) { accR[i] = br[col]; accZ[i] = bz[col]; }
    #pragma unroll 8
    for (int k = 0; k < 192; k++) {
        float wr = smf[GRU_WR + k*64 + col];
        float wz = smf[GRU_WZ + k*64 + col];
        #pragma unroll
        for (int i = 0; i < 4; i++) {
            float v = sa[(rg*4 + i)*192 + k];
            accR[i] += v*wr; accZ[i] += v*wz;
        }
    }
    float zg[4], hold[4];
    #pragma unroll
    for (int i = 0; i < 4; i++) {
        int r = rg*4 + i;
        float rr = sigf(accR[i]);
        zg[i] = sigf(accZ[i]);
        hold[i] = sa[r*192 + 128 + col];
        smf[GRU_RH + r*64 + col] = rr * hold[i];
    }
    __syncthreads();

    float accH[4];
    #pragma unroll
    for (int i = 0; i < 4; i++) accH[i] = bh[col];
    #pragma unroll 8
    for (int k = 0; k < 128; k++) {
        float wh = smf[GRU_WH + k*64 + col];
        #pragma unroll
        for (int i = 0; i < 4; i++) accH[i] += sa[(rg*4 + i)*192 + k]*wh;
    }
    #pragma unroll 8
    for (int k = 0; k < 64; k++) {
        float wh = smf[GRU_WH + (128 + k)*64 + col];
        #pragma unroll
        for (int i = 0; i < 4; i++) accH[i] += smf[GRU_RH + (rg*4 + i)*64 + k]*wh;
    }
    float* hw = g_h + (size_t)(b*NN + n0)*64;
    #pragma unroll
    for (int i = 0; i < 4; i++) {
        int r = rg*4 + i;
        float hh = tanhf(accH[i]);
        hw[r*64 + col] = (1.0f - zg[i])*hold[i] + zg[i]*hh;
    }
}

// ---------------- readout ----------------
__global__ void k_out(const float* __restrict__ ann, const float* __restrict__ Wo1,
                      const float* __restrict__ bo1, const float* __restrict__ Wo2,
                      const float* __restrict__ bo2, float* __restrict__ out) {
    __shared__ float sx[4][80];
    __shared__ float sred[128];
    int blk = blockIdx.x;
    int b = blk >> 9;
    int n0 = (blk & 511) * 4;
    int tid = threadIdx.x;
    for (int i = tid; i < 256; i += 128) {
        int r = i >> 6, c = i & 63;
        sx[r][c] = g_h[(b*NN + n0 + r)*64 + c];
    }
    if (tid < 64) {
        int r = tid >> 4, c = tid & 15;
        sx[r][64 + c] = ann[(b*NN + n0 + r)*AAN + c];
    }
    __syncthreads();
    float v[4];
    float w2 = Wo2[tid], b1 = bo1[tid];
    #pragma unroll
    for (int r = 0; r < 4; r++) {
        float acc = b1;
        #pragma unroll 10
        for (int k = 0; k < 80; k++) acc += sx[r][k]*Wo1[k*128 + tid];
        v[r] = w2 * sigf(acc);
    }
    #pragma unroll
    for (int r = 0; r < 4; r++) {
        sred[tid] = v[r];
        __syncthreads();
        for (int s = 64; s > 0; s >>= 1) {
            if (tid < s) sred[tid] += sred[tid + s];
            __syncthreads();
        }
        if (tid == 0) out[b*NN + n0 + r] = sred[0] + bo2[0];
        __syncthreads();
    }
}

extern "C" void kernel_launch(void* const* d_in, const int* in_sizes, int n_in,
                              void* d_out, int out_size) {
    const float* prop = (const float*)d_in[0];
    const float* ann  = (const float*)d_in[1];
    const float* adj  = (const float*)d_in[2];
    const float* Win  = (const float*)d_in[3];
    const float* bin  = (const float*)d_in[4];
    const float* Wout = (const float*)d_in[5];
    const float* bout = (const float*)d_in[6];
    const float* Wr   = (const float*)d_in[7];
    const float* br   = (const float*)d_in[8];
    const float* Wz   = (const float*)d_in[9];
    const float* bz   = (const float*)d_in[10];
    const float* Wh   = (const float*)d_in[11];
    const float* bh   = (const float*)d_in[12];
    const float* Wo1  = (const float*)d_in[13];
    const float* bo1  = (const float*)d_in[14];
    const float* Wo2  = (const float*)d_in[15];
    const float* bo2  = (const float*)d_in[16];
    float* out = (float*)d_out;

    cudaFuncSetAttribute(k_gemm, cudaFuncAttributeMaxDynamicSharedMemorySize, SMEM_GEMM);
    cudaFuncSetAttribute(k_gru,  cudaFuncAttributeMaxDynamicSharedMemorySize, SMEM_GRU);

    k_init<<<256, 256>>>((const float4*)prop);
    k_round<<<8192, 256>>>((const float4*)adj);
    for (int t = 0; t < TT; t++) {
        k_transform<<<dim3(64, EE, BB), 256>>>(Win, bin, Wout, bout);
        k_gemm<<<dim3(32, 2, BB*KSPL), 128, SMEM_GEMM>>>();
        k_gru<<<dim3(64, BB), 512, SMEM_GRU>>>(Wr, br, Wz, bz, Wh, bh);
    }
    k_out<<<1024, 128>>>(ann, Wo1, bo1, Wo2, bo2, out);
}

// round 7
// speedup vs baseline: 5.3443x; 1.4734x over previous
#include <cuda_runtime.h>
#include <cuda_fp16.h>
#include <cstdint>

#define BB 2
#define NN 2048
#define DD 64
#define AAN 16
#define EE 2
#define TT 5
#define HH 128
#define EN (EE*NN)       /* 4096 */
#define ADJW (2*EN)      /* 8192 */
#define KSPL 4
#define KLEN (EN/KSPL)   /* 1024 */
#define KCH  (KLEN/32)   /* 32 chunks of K=32 */

// ---------------- device scratch (no allocation allowed) ----------------
__device__ __half g_adjH[(size_t)BB*NN*ADJW];      // adj RN-rounded to fp16
__device__ float  g_h[BB*NN*DD];
__device__ __half g_msgT[2*BB*DD*EN];              // [dir][b][d][m], fp16
__device__ float  g_ain[KSPL*BB*NN*DD];            // K-split partials (fp32)
__device__ float  g_aout[KSPL*BB*NN*DD];

__device__ __forceinline__ float sigf(float x){ return 1.0f/(1.0f+__expf(-x)); }
__device__ __forceinline__ uint32_t s2u(const void* p){
    uint32_t a; asm("{ .reg .u64 t; cvta.to.shared.u64 t, %1; cvt.u32.u64 %0, t; }":"=r"(a):"l"(p)); return a;
}
__device__ __forceinline__ void cpa16(uint32_t d, const void* s){
    asm volatile("cp.async.cg.shared.global [%0], [%1], 16;"::"r"(d),"l"(s));
}
#define CPCOMMIT() asm volatile("cp.async.commit_group;":::"memory")
#define CPWAIT(n)  asm volatile("cp.async.wait_group %0;"::"n"(n):"memory")

__device__ __forceinline__ void ldsm4(uint32_t& r0, uint32_t& r1, uint32_t& r2, uint32_t& r3, uint32_t a){
    asm volatile("ldmatrix.sync.aligned.m8n8.x4.shared.b16 {%0,%1,%2,%3}, [%4];"
                 : "=r"(r0),"=r"(r1),"=r"(r2),"=r"(r3) : "r"(a));
}
__device__ __forceinline__ void mma16(float* c, const uint32_t* a, const uint32_t* b){
    asm volatile("mma.sync.aligned.m16n8k16.row.col.f32.f16.f16.f32 "
                 "{%0,%1,%2,%3},{%4,%5,%6,%7},{%8,%9},{%0,%1,%2,%3};"
                 : "+f"(c[0]),"+f"(c[1]),"+f"(c[2]),"+f"(c[3])
                 : "r"(a[0]),"r"(a[1]),"r"(a[2]),"r"(a[3]),"r"(b[0]),"r"(b[1]));
}

// ---------------- init / round (fp32 adj -> fp16) ----------------
__global__ void k_init(const float4* __restrict__ ps) {
    int i = blockIdx.x*256 + threadIdx.x;
    ((float4*)g_h)[i] = ps[i];
}
__global__ void k_round(const float4* __restrict__ adj) {
    int i0 = blockIdx.x*1024 + threadIdx.x;
    uint2* dst = (uint2*)g_adjH;
    #pragma unroll
    for (int j = 0; j < 4; j++) {
        int idx = i0 + j*256;
        float4 v = adj[idx];
        __half2 h01 = __floats2half2_rn(v.x, v.y);
        __half2 h23 = __floats2half2_rn(v.z, v.w);
        dst[idx] = make_uint2(*(uint32_t*)&h01, *(uint32_t*)&h23);
    }
}

// ---------------- transform: msgT[io][b][d][e*2048+n] = fp16( h@W_io[e] + b_io[e] ) ----------------
__global__ void k_transform(const float* __restrict__ Win, const float* __restrict__ bin,
                            const float* __restrict__ Wout, const float* __restrict__ bout) {
    __shared__ float sh[32*64];
    __shared__ float sWi[64*64], sWo[64*64];
    __shared__ float sT[64*33];
    __shared__ float sbi[64], sbo[64];
    int nt = blockIdx.x, e = blockIdx.y, b = blockIdx.z;
    int tid = threadIdx.x;

    const float4* h4 = (const float4*)(g_h + (b*NN + nt*32)*64);
    #pragma unroll
    for (int i = 0; i < 2; i++) ((float4*)sh)[tid + i*256] = h4[tid + i*256];
    const float4* wi4 = (const float4*)(Win + e*4096);
    const float4* wo4 = (const float4*)(Wout + e*4096);
    #pragma unroll
    for (int i = 0; i < 4; i++) {
        ((float4*)sWi)[tid + i*256] = wi4[tid + i*256];
        ((float4*)sWo)[tid + i*256] = wo4[tid + i*256];
    }
    if (tid < 64) { sbi[tid] = bin[e*64 + tid]; sbo[tid] = bout[e*64 + tid]; }
    __syncthreads();

    int col = tid & 63, rg = tid >> 6;
    for (int io = 0; io < 2; io++) {
        if (io) __syncthreads();
        const float* w = io ? sWo : sWi;
        const float* bb = io ? sbo : sbi;
        #pragma unroll
        for (int ii = 0; ii < 8; ii++) {
            int r = rg + 4*ii;
            float acc = bb[col];
            #pragma unroll
            for (int k = 0; k < 64; k++) acc += sh[r*64 + k] * w[k*64 + col];
            sT[col*33 + r] = acc;
        }
        __syncthreads();
        __half* dst = g_msgT + ((size_t)(io*BB + b))*(DD*(size_t)EN) + e*NN + nt*32;
        #pragma unroll
        for (int i = 0; i < 8; i++) {
            int idx = tid + i*256;
            int d = idx >> 5, n = idx & 31;
            dst[(size_t)d*EN + n] = __float2half_rn(sT[d*33 + n]);
        }
    }
}

// ---------------- GEMM fp16 (K-split x4): Cpart[128x64] += adjH[128x1024] @ msg[1024x64] ----------------
// grid (16 mtiles, 2 dir, 8), 256 thr (8 warps, 4x2 of 32x32), NSTG=5, ldmatrix feeds
#define ASTG 10240                 /* 128 rows * 80 B */
#define BSTG 5120                  /* 64 rows * 80 B  */
#define STGB (ASTG + BSTG)         /* 15360 B */
#define NSTG 5
#define SMEM_GEMM (NSTG*STGB)      /* 76800 B */

__global__ __launch_bounds__(256, 2) void k_gemm() {
    extern __shared__ char smc[];
    uint32_t usm = s2u(smc);
    int tid = threadIdx.x;
    int wid = tid >> 5, lane = tid & 31;
    int lr = lane >> 2, lc = lane & 3;
    int wm = wid & 3, wn = wid >> 2;
    int mt = blockIdx.x, dir = blockIdx.y;
    int b = blockIdx.z >> 2, ks = blockIdx.z & 3;
    int m0 = mt * 128;

    const __half* aBase = g_adjH + ((size_t)(b*NN + m0))*ADJW + (size_t)dir*EN + ks*KLEN;
    const __half* bBase = g_msgT + ((size_t)(dir*BB + b))*(DD*(size_t)EN) + ks*KLEN;

    // per-lane ldmatrix byte offsets (within stage)
    uint32_t aOff = (uint32_t)((wm*32 + (lane & 15))*80 + (lane >> 4)*16);
    uint32_t bOff = (uint32_t)((wn*32 + ((lane >> 4)*8) + (lane & 7))*80 + ((lane >> 3) & 1)*16);

    auto fill = [&](int stage, int c) {
        uint32_t ab = usm + stage*STGB;
        uint32_t bb = ab + ASTG;
        const __half* as = aBase + c*32;
        const __half* bs = bBase + c*32;
        #pragma unroll
        for (int i = 0; i < 2; i++) {
            int idx = tid + i*256;              // 512 ops: r 0..127, q 0..3
            int r = idx >> 2, q = idx & 3;
            cpa16(ab + r*80 + q*16, as + (size_t)r*ADJW + q*8);
        }
        {
            int r = tid >> 2, q = tid & 3;      // 256 ops: r 0..63
            cpa16(bb + r*80 + q*16, bs + (size_t)r*EN + q*8);
        }
        CPCOMMIT();
    };

    #pragma unroll
    for (int s = 0; s < 4; s++) fill(s, s);

    float acc[2][4][4];
    #pragma unroll
    for (int i = 0; i < 2; i++)
        #pragma unroll
        for (int j = 0; j < 4; j++)
            #pragma unroll
            for (int q = 0; q < 4; q++) acc[i][j][q] = 0.f;

    int st = 0;
    for (int c = 0; c < KCH; c++) {
        int rem = KCH - 1 - c;
        if (rem >= 3) CPWAIT(3); else if (rem == 2) CPWAIT(2);
        else if (rem == 1) CPWAIT(1); else CPWAIT(0);
        __syncthreads();
        if (c + 4 < KCH) {
            int st4 = st + 4; if (st4 >= NSTG) st4 -= NSTG;
            fill(st4, c + 4);
        }

        uint32_t ab = usm + st*STGB;
        uint32_t bb = ab + ASTG;
        #pragma unroll
        for (int k16 = 0; k16 < 2; k16++) {
            uint32_t af[2][4], bf[4][2];
            #pragma unroll
            for (int mf = 0; mf < 2; mf++)
                ldsm4(af[mf][0], af[mf][1], af[mf][2], af[mf][3],
                      ab + aOff + mf*1280 + k16*32);
            #pragma unroll
            for (int bg = 0; bg < 2; bg++) {
                uint32_t r0, r1, r2, r3;
                ldsm4(r0, r1, r2, r3, bb + bOff + bg*1280 + k16*32);
                bf[bg*2][0] = r0;   bf[bg*2][1] = r1;
                bf[bg*2+1][0] = r2; bf[bg*2+1][1] = r3;
            }
            #pragma unroll
            for (int mf = 0; mf < 2; mf++)
                #pragma unroll
                for (int nf = 0; nf < 4; nf++)
                    mma16(acc[mf][nf], af[mf], bf[nf]);
        }
        st = (st + 1 >= NSTG) ? 0 : st + 1;
    }

    float* dst = (dir ? g_aout : g_ain) + (size_t)ks*BB*NN*DD + (size_t)b*NN*64;
    #pragma unroll
    for (int mf = 0; mf < 2; mf++) {
        #pragma unroll
        for (int nf = 0; nf < 4; nf++) {
            int row = m0 + wm*32 + mf*16 + lr;
            int colg = wn*32 + nf*8 + lc*2;
            *(float2*)(dst + (size_t)row*64 + colg)     = make_float2(acc[mf][nf][0], acc[mf][nf][1]);
            *(float2*)(dst + (size_t)(row+8)*64 + colg) = make_float2(acc[mf][nf][2], acc[mf][nf][3]);
        }
    }
}

// ---------------- GRU: weights smem-staged; sums the four K-split partials ----------------
#define GRU_WR 0
#define GRU_WZ 12288
#define GRU_WH 24576
#define GRU_SA 36864              /* 32*192 */
#define GRU_RH 43008              /* 32*64  */
#define SMEM_GRU ((GRU_RH + 2048)*4)   /* 180224 B */

__global__ __launch_bounds__(512, 1) void k_gru(
        const float* __restrict__ Wr, const float* __restrict__ br,
        const float* __restrict__ Wz, const float* __restrict__ bz,
        const float* __restrict__ Wh, const float* __restrict__ bh) {
    extern __shared__ float smf[];
    int nt = blockIdx.x, b = blockIdx.y;
    int tid = threadIdx.x;
    int n0 = nt * 32;

    #pragma unroll
    for (int i = 0; i < 6; i++) {
        int idx = tid + i*512;
        ((float4*)(smf + GRU_WR))[idx] = ((const float4*)Wr)[idx];
        ((float4*)(smf + GRU_WZ))[idx] = ((const float4*)Wz)[idx];
        ((float4*)(smf + GRU_WH))[idx] = ((const float4*)Wh)[idx];
    }
    const float* ain0  = g_ain  + (size_t)(b*NN + n0)*64;
    const float* aout0 = g_aout + (size_t)(b*NN + n0)*64;
    const float* hp    = g_h    + (size_t)(b*NN + n0)*64;
    const size_t PSTR = (size_t)BB*NN*DD;
    #pragma unroll
    for (int i = 0; i < 4; i++) {
        int idx = tid + i*512;
        int r = idx >> 6, c = idx & 63;
        float si = 0.f, so = 0.f;
        #pragma unroll
        for (int p = 0; p < KSPL; p++) {
            si += ain0[p*PSTR + r*64 + c];
            so += aout0[p*PSTR + r*64 + c];
        }
        smf[GRU_SA + r*192 + c]       = si;
        smf[GRU_SA + r*192 + 64 + c]  = so;
        smf[GRU_SA + r*192 + 128 + c] = hp[r*64 + c];
    }
    __syncthreads();

    int col = tid & 63, rg = tid >> 6;
    const float* sa = smf + GRU_SA;
    float accR[4], accZ[4];
    #pragma unroll
    for (int i = 0; i < 4; i++) { accR[i] = br[col]; accZ[i] = bz[col]; }
    #pragma unroll 8
    for (int k = 0; k < 192; k++) {
        float wr = smf[GRU_WR + k*64 + col];
        float wz = smf[GRU_WZ + k*64 + col];
        #pragma unroll
        for (int i = 0; i < 4; i++) {
            float v = sa[(rg*4 + i)*192 + k];
            accR[i] += v*wr; accZ[i] += v*wz;
        }
    }
    float zg[4], hold[4];
    #pragma unroll
    for (int i = 0; i < 4; i++) {
        int r = rg*4 + i;
        float rr = sigf(accR[i]);
        zg[i] = sigf(accZ[i]);
        hold[i] = sa[r*192 + 128 + col];
        smf[GRU_RH + r*64 + col] = rr * hold[i];
    }
    __syncthreads();

    float accH[4];
    #pragma unroll
    for (int i = 0; i < 4; i++) accH[i] = bh[col];
    #pragma unroll 8
    for (int k = 0; k < 128; k++) {
        float wh = smf[GRU_WH + k*64 + col];
        #pragma unroll
        for (int i = 0; i < 4; i++) accH[i] += sa[(rg*4 + i)*192 + k]*wh;
    }
    #pragma unroll 8
    for (int k = 0; k < 64; k++) {
        float wh = smf[GRU_WH + (128 + k)*64 + col];
        #pragma unroll
        for (int i = 0; i < 4; i++) accH[i] += smf[GRU_RH + (rg*4 + i)*64 + k]*wh;
    }
    float* hw = g_h + (size_t)(b*NN + n0)*64;
    #pragma unroll
    for (int i = 0; i < 4; i++) {
        int r = rg*4 + i;
        float hh = tanhf(accH[i]);
        hw[r*64 + col] = (1.0f - zg[i])*hold[i] + zg[i]*hh;
    }
}

// ---------------- readout ----------------
__global__ void k_out(const float* __restrict__ ann, const float* __restrict__ Wo1,
                      const float* __restrict__ bo1, const float* __restrict__ Wo2,
                      const float* __restrict__ bo2, float* __restrict__ out) {
    __shared__ float sx[4][80];
    __shared__ float sred[128];
    int blk = blockIdx.x;
    int b = blk >> 9;
    int n0 = (blk & 511) * 4;
    int tid = threadIdx.x;
    for (int i = tid; i < 256; i += 128) {
        int r = i >> 6, c = i & 63;
        sx[r][c] = g_h[(b*NN + n0 + r)*64 + c];
    }
    if (tid < 64) {
        int r = tid >> 4, c = tid & 15;
        sx[r][64 + c] = ann[(b*NN + n0 + r)*AAN + c];
    }
    __syncthreads();
    float v[4];
    float w2 = Wo2[tid], b1 = bo1[tid];
    #pragma unroll
    for (int r = 0; r < 4; r++) {
        float acc = b1;
        #pragma unroll 10
        for (int k = 0; k < 80; k++) acc += sx[r][k]*Wo1[k*128 + tid];
        v[r] = w2 * sigf(acc);
    }
    #pragma unroll
    for (int r = 0; r < 4; r++) {
        sred[tid] = v[r];
        __syncthreads();
        for (int s = 64; s > 0; s >>= 1) {
            if (tid < s) sred[tid] += sred[tid + s];
            __syncthreads();
        }
        if (tid == 0) out[b*NN + n0 + r] = sred[0] + bo2[0];
        __syncthreads();
    }
}

extern "C" void kernel_launch(void* const* d_in, const int* in_sizes, int n_in,
                              void* d_out, int out_size) {
    const float* prop = (const float*)d_in[0];
    const float* ann  = (const float*)d_in[1];
    const float* adj  = (const float*)d_in[2];
    const float* Win  = (const float*)d_in[3];
    const float* bin  = (const float*)d_in[4];
    const float* Wout = (const float*)d_in[5];
    const float* bout = (const float*)d_in[6];
    const float* Wr   = (const float*)d_in[7];
    const float* br   = (const float*)d_in[8];
    const float* Wz   = (const float*)d_in[9];
    const float* bz   = (const float*)d_in[10];
    const float* Wh   = (const float*)d_in[11];
    const float* bh   = (const float*)d_in[12];
    const float* Wo1  = (const float*)d_in[13];
    const float* bo1  = (const float*)d_in[14];
    const float* Wo2  = (const float*)d_in[15];
    const float* bo2  = (const float*)d_in[16];
    float* out = (float*)d_out;

    cudaFuncSetAttribute(k_gemm, cudaFuncAttributeMaxDynamicSharedMemorySize, SMEM_GEMM);
    cudaFuncSetAttribute(k_gru,  cudaFuncAttributeMaxDynamicSharedMemorySize, SMEM_GRU);

    k_init<<<256, 256>>>((const float4*)prop);
    k_round<<<8192, 256>>>((const float4*)adj);
    for (int t = 0; t < TT; t++) {
        k_transform<<<dim3(64, EE, BB), 256>>>(Win, bin, Wout, bout);
        k_gemm<<<dim3(16, 2, BB*KSPL), 256, SMEM_GEMM>>>();
        k_gru<<<dim3(64, BB), 512, SMEM_GRU>>>(Wr, br, Wz, bz, Wh, bh);
    }
    k_out<<<1024, 128>>>(ann, Wo1, bo1, Wo2, bo2, out);
}